// round 14
// baseline (speedup 1.0000x reference)
#include <cuda_runtime.h>
#include <math.h>

#define N_NODES 100000
#define N_EDGES 3200000
#define D_IN    128
#define D_HID   16
#define D_OUT   2

// ---------------- constant weights (D2D copies at launch) ----------------
__constant__ float cW1[D_IN * D_HID];
__constant__ float cW2[D_HID * D_OUT];
__constant__ float cb1[D_HID];
__constant__ float cb2[D_OUT];

// ---------------- scratch ----------------
__device__ int   g_deg [N_NODES];           // zeroed via memset; deg = count+1
__device__ float g_dinv[N_NODES];           // computed inside gemm1
__device__ float g_h1  [N_NODES * D_HID];   // (x @ W1) * dinv
__device__ float g_agg1[N_NODES * D_HID];   // zeroed inside gemm1
__device__ float g_g2  [N_NODES * D_OUT];   // (h2 @ W2) * dinv
__device__ float g_agg2[N_NODES * D_OUT];   // zeroed via memset

// ---------------- degree histogram (self loop added at use) ----------------
__global__ void deg_kernel(const int* __restrict__ ei) {
    int e = blockIdx.x * blockDim.x + threadIdx.x;
    if (e >= N_EDGES) return;
    atomicAdd(&g_deg[ei[N_EDGES + e]], 1);
}

// ---------------- GEMM1: h1 = (x @ W1) * dinv, split-k x2 ----------------
// 256 threads cover 128 nodes. Warps 0-3 (half=0) handle k in [0,64),
// warps 4-7 (half=1) handle k in [64,128). `half` is warp-uniform, so the
// cW1 accesses remain broadcast (the R10 regression was lane-varying).
// half=1 writes partials to padded smem; half=0 combines, computes dinv,
// stores h1 and zeroes this node's agg1 row.
__global__ void __launch_bounds__(256) gemm1_kernel(const float* __restrict__ x) {
    __shared__ float sP[128 * 20];          // 20-float rows: conflict-free float4
    const int t    = threadIdx.x;
    const int half = t >> 7;                // warp-uniform
    const int ln   = t & 127;
    const int node = blockIdx.x * 128 + ln;
    const bool valid = node < N_NODES;

    float acc[D_HID];
#pragma unroll
    for (int j = 0; j < D_HID; j++) acc[j] = 0.0f;

    if (valid) {
        const float4* xr = (const float4*)(x + (size_t)node * D_IN) + half * 16;
#pragma unroll
        for (int k4 = 0; k4 < 16; k4++) {
            float4 xv = xr[k4];
            float xs[4] = {xv.x, xv.y, xv.z, xv.w};
#pragma unroll
            for (int kk = 0; kk < 4; kk++) {
                const float* w = &cW1[((half * 16 + k4) * 4 + kk) * D_HID];
#pragma unroll
                for (int j = 0; j < D_HID; j++)
                    acc[j] = fmaf(xs[kk], w[j], acc[j]);
            }
        }
    }

    if (half == 1) {
        float* row = &sP[ln * 20];
#pragma unroll
        for (int j4 = 0; j4 < 4; j4++)
            *(float4*)&row[j4 * 4] = make_float4(acc[j4 * 4 + 0], acc[j4 * 4 + 1],
                                                 acc[j4 * 4 + 2], acc[j4 * 4 + 3]);
    }
    __syncthreads();
    if (half == 0 && valid) {
        const float* row = &sP[ln * 20];
        const float di = rsqrtf((float)(g_deg[node] + 1));
        g_dinv[node] = di;
        float4* out = (float4*)&g_h1[(size_t)node * D_HID];
        float4* az  = (float4*)&g_agg1[(size_t)node * D_HID];
        const float4 z4 = make_float4(0.f, 0.f, 0.f, 0.f);
#pragma unroll
        for (int j4 = 0; j4 < 4; j4++) {
            float4 p = *(const float4*)&row[j4 * 4];
            out[j4] = make_float4((acc[j4 * 4 + 0] + p.x) * di,
                                  (acc[j4 * 4 + 1] + p.y) * di,
                                  (acc[j4 * 4 + 2] + p.z) * di,
                                  (acc[j4 * 4 + 3] + p.w) * di);
            az[j4] = z4;
        }
    }
}

// ---------------- vector reductions ----------------
__device__ __forceinline__ void red_v4(float* p, float4 v) {
    asm volatile("red.global.add.v4.f32 [%0], {%1,%2,%3,%4};"
                 :: "l"(p), "f"(v.x), "f"(v.y), "f"(v.z), "f"(v.w) : "memory");
}
__device__ __forceinline__ void red_v2(float* p, float a, float b) {
    asm volatile("red.global.add.v2.f32 [%0], {%1,%2};"
                 :: "l"(p), "f"(a), "f"(b) : "memory");
}

// ----- layer-1 aggregation: 4 lanes per edge (coalesced 64B gather + RED) -----
__global__ void __launch_bounds__(256) agg1_kernel(const int* __restrict__ ei) {
    int gt  = blockIdx.x * 256 + threadIdx.x;
    int e   = gt >> 2;
    int sub = gt & 3;
    if (e >= N_EDGES) return;
    int s = ei[e];
    int d = ei[N_EDGES + e];
    float4 v = *(const float4*)&g_h1[(size_t)s * D_HID + sub * 4];
    red_v4(&g_agg1[(size_t)d * D_HID + sub * 4], v);
}

// ------- fused: h2 = relu(dinv*(agg1 + h1) + b1); g2 = (h2 @ W2)*dinv -------
__global__ void project_kernel() {
    int i = blockIdx.x * blockDim.x + threadIdx.x;
    if (i >= N_NODES) return;
    float di = g_dinv[i];
    const float4* a4 = (const float4*)&g_agg1[(size_t)i * D_HID];
    const float4* h4 = (const float4*)&g_h1[(size_t)i * D_HID];
    float z0 = 0.f, z1 = 0.f;
#pragma unroll
    for (int j4 = 0; j4 < 4; j4++) {
        float4 a = a4[j4];
        float4 h = h4[j4];
        float hv[4] = {a.x + h.x, a.y + h.y, a.z + h.z, a.w + h.w};
#pragma unroll
        for (int k = 0; k < 4; k++) {
            int j = j4 * 4 + k;
            float h2 = fmaxf(fmaf(di, hv[k], cb1[j]), 0.f);
            z0 = fmaf(h2, cW2[j * D_OUT + 0], z0);
            z1 = fmaf(h2, cW2[j * D_OUT + 1], z1);
        }
    }
    g_g2[i * 2 + 0] = z0 * di;
    g_g2[i * 2 + 1] = z1 * di;
}

// ---------------- layer-2 aggregation: one thread per edge ----------------
__global__ void agg2_kernel(const int* __restrict__ ei) {
    int e = blockIdx.x * blockDim.x + threadIdx.x;
    if (e >= N_EDGES) return;
    int s = ei[e];
    int d = ei[N_EDGES + e];
    float2 m = *(const float2*)&g_g2[s * 2];
    red_v2(&g_agg2[d * 2], m.x, m.y);
}

// ---------------- final: post-scale, bias, log_softmax ----------------
__global__ void final_kernel(float* __restrict__ out) {
    int i = blockIdx.x * blockDim.x + threadIdx.x;
    if (i >= N_NODES) return;
    float di = g_dinv[i];
    float z0 = fmaf(di, g_agg2[i * 2 + 0] + g_g2[i * 2 + 0], cb2[0]);
    float z1 = fmaf(di, g_agg2[i * 2 + 1] + g_g2[i * 2 + 1], cb2[1]);
    float m  = fmaxf(z0, z1);
    float lse = m + logf(expf(z0 - m) + expf(z1 - m));
    out[i * 2 + 0] = z0 - lse;
    out[i * 2 + 1] = z1 - lse;
}

// ---------------- launch ----------------
extern "C" void kernel_launch(void* const* d_in, const int* in_sizes, int n_in,
                              void* d_out, int out_size) {
    const float* x  = (const float*)d_in[0];
    const float* W1 = (const float*)d_in[1];
    const float* b1 = (const float*)d_in[2];
    const float* W2 = (const float*)d_in[3];
    const float* b2 = (const float*)d_in[4];
    const int*   ei = (const int*)d_in[5];
    float* out = (float*)d_out;

    cudaMemcpyToSymbolAsync(cW1, W1, D_IN * D_HID * sizeof(float), 0, cudaMemcpyDeviceToDevice);
    cudaMemcpyToSymbolAsync(cW2, W2, D_HID * D_OUT * sizeof(float), 0, cudaMemcpyDeviceToDevice);
    cudaMemcpyToSymbolAsync(cb1, b1, D_HID * sizeof(float), 0, cudaMemcpyDeviceToDevice);
    cudaMemcpyToSymbolAsync(cb2, b2, D_OUT * sizeof(float), 0, cudaMemcpyDeviceToDevice);

    void* p_deg  = nullptr;
    void* p_agg2 = nullptr;
    cudaGetSymbolAddress(&p_deg,  g_deg);
    cudaGetSymbolAddress(&p_agg2, g_agg2);
    cudaMemsetAsync(p_deg,  0, N_NODES * sizeof(int));
    cudaMemsetAsync(p_agg2, 0, N_NODES * D_OUT * sizeof(float));

    const int T = 256;
    deg_kernel<<<(N_EDGES + T - 1) / T, T>>>(ei);
    gemm1_kernel<<<(N_NODES + 127) / 128, 256>>>(x);
    agg1_kernel<<<(N_EDGES * 4 + 255) / 256, 256>>>(ei);
    project_kernel<<<(N_NODES + T - 1) / T, T>>>();
    agg2_kernel<<<(N_EDGES + T - 1) / T, T>>>(ei);
    final_kernel<<<(N_NODES + T - 1) / T, T>>>(out);
}

// round 15
// speedup vs baseline: 1.1343x; 1.1343x over previous
#include <cuda_runtime.h>
#include <math.h>

#define N_NODES 100000
#define N_EDGES 3200000
#define D_IN    128
#define D_HID   16
#define D_OUT   2

// ---------------- constant weights (D2D copies at launch) ----------------
__constant__ float cW1[D_IN * D_HID];
__constant__ float cW2[D_HID * D_OUT];
__constant__ float cb1[D_HID];
__constant__ float cb2[D_OUT];

// ---------------- scratch ----------------
__device__ int   g_deg [N_NODES];           // zeroed via memset; deg = count+1
__device__ float g_dinv[N_NODES];           // computed in gemm1 epilogue
__device__ float g_h1  [N_NODES * D_HID];   // (x @ W1) * dinv
__device__ float g_agg1[N_NODES * D_HID];   // zeroed inside gemm1
__device__ float g_g2  [N_NODES * D_OUT];   // (h2 @ W2) * dinv
__device__ float g_agg2[N_NODES * D_OUT];   // zeroed inside project_kernel

// ---------------- degree histogram (self loop added at use) ----------------
__global__ void deg_kernel(const int* __restrict__ ei) {
    int e = blockIdx.x * blockDim.x + threadIdx.x;
    if (e >= N_EDGES) return;
    atomicAdd(&g_deg[ei[N_EDGES + e]], 1);
}

// ---------------- GEMM1: h1 = (x @ W1) * dinv, one thread per node ----------------
// W1 in constant memory (warp-uniform -> broadcast). Epilogue computes dinv
// from the degree histogram and zeroes this node's agg1 row.
__global__ void __launch_bounds__(256) gemm1_kernel(const float* __restrict__ x) {
    const int node = blockIdx.x * 256 + threadIdx.x;
    if (node >= N_NODES) return;
    const float4* xr = (const float4*)(x + (size_t)node * D_IN);

    float acc[D_HID];
#pragma unroll
    for (int j = 0; j < D_HID; j++) acc[j] = 0.0f;

#pragma unroll 8
    for (int k4 = 0; k4 < D_IN / 4; k4++) {
        float4 xv = xr[k4];
        float xs[4] = {xv.x, xv.y, xv.z, xv.w};
#pragma unroll
        for (int kk = 0; kk < 4; kk++) {
            const float* w = &cW1[(k4 * 4 + kk) * D_HID];
#pragma unroll
            for (int j = 0; j < D_HID; j++)
                acc[j] = fmaf(xs[kk], w[j], acc[j]);
        }
    }

    const float di = rsqrtf((float)(g_deg[node] + 1));
    g_dinv[node] = di;
    float4* out = (float4*)&g_h1[(size_t)node * D_HID];
    float4* az  = (float4*)&g_agg1[(size_t)node * D_HID];
    const float4 z4 = make_float4(0.f, 0.f, 0.f, 0.f);
#pragma unroll
    for (int j4 = 0; j4 < 4; j4++) {
        out[j4] = make_float4(acc[j4 * 4 + 0] * di, acc[j4 * 4 + 1] * di,
                              acc[j4 * 4 + 2] * di, acc[j4 * 4 + 3] * di);
        az[j4]  = z4;
    }
}

// ---------------- vector reductions ----------------
__device__ __forceinline__ void red_v4(float* p, float4 v) {
    asm volatile("red.global.add.v4.f32 [%0], {%1,%2,%3,%4};"
                 :: "l"(p), "f"(v.x), "f"(v.y), "f"(v.z), "f"(v.w) : "memory");
}
__device__ __forceinline__ void red_v2(float* p, float a, float b) {
    asm volatile("red.global.add.v2.f32 [%0], {%1,%2};"
                 :: "l"(p), "f"(a), "f"(b) : "memory");
}

// ----- layer-1 aggregation: 4 lanes per edge (coalesced 64B gather + RED) -----
__global__ void __launch_bounds__(256) agg1_kernel(const int* __restrict__ ei) {
    int gt  = blockIdx.x * 256 + threadIdx.x;
    int e   = gt >> 2;
    int sub = gt & 3;
    if (e >= N_EDGES) return;
    int s = ei[e];
    int d = ei[N_EDGES + e];
    float4 v = *(const float4*)&g_h1[(size_t)s * D_HID + sub * 4];
    red_v4(&g_agg1[(size_t)d * D_HID + sub * 4], v);
}

// ------- fused: h2 = relu(dinv*(agg1 + h1) + b1); g2 = (h2 @ W2)*dinv -------
// Also zeroes g_agg2 for this node (runs strictly before agg2_kernel).
__global__ void project_kernel() {
    int i = blockIdx.x * blockDim.x + threadIdx.x;
    if (i >= N_NODES) return;
    float di = g_dinv[i];
    const float4* a4 = (const float4*)&g_agg1[(size_t)i * D_HID];
    const float4* h4 = (const float4*)&g_h1[(size_t)i * D_HID];
    float z0 = 0.f, z1 = 0.f;
#pragma unroll
    for (int j4 = 0; j4 < 4; j4++) {
        float4 a = a4[j4];
        float4 h = h4[j4];
        float hv[4] = {a.x + h.x, a.y + h.y, a.z + h.z, a.w + h.w};
#pragma unroll
        for (int k = 0; k < 4; k++) {
            int j = j4 * 4 + k;
            float h2 = fmaxf(fmaf(di, hv[k], cb1[j]), 0.f);
            z0 = fmaf(h2, cW2[j * D_OUT + 0], z0);
            z1 = fmaf(h2, cW2[j * D_OUT + 1], z1);
        }
    }
    g_g2[i * 2 + 0] = z0 * di;
    g_g2[i * 2 + 1] = z1 * di;
    *(float2*)&g_agg2[i * 2] = make_float2(0.f, 0.f);
}

// ---------------- layer-2 aggregation: one thread per edge ----------------
__global__ void agg2_kernel(const int* __restrict__ ei) {
    int e = blockIdx.x * blockDim.x + threadIdx.x;
    if (e >= N_EDGES) return;
    int s = ei[e];
    int d = ei[N_EDGES + e];
    float2 m = *(const float2*)&g_g2[s * 2];
    red_v2(&g_agg2[d * 2], m.x, m.y);
}

// ---------------- final: post-scale, bias, log_softmax ----------------
__global__ void final_kernel(float* __restrict__ out) {
    int i = blockIdx.x * blockDim.x + threadIdx.x;
    if (i >= N_NODES) return;
    float di = g_dinv[i];
    float z0 = fmaf(di, g_agg2[i * 2 + 0] + g_g2[i * 2 + 0], cb2[0]);
    float z1 = fmaf(di, g_agg2[i * 2 + 1] + g_g2[i * 2 + 1], cb2[1]);
    float m  = fmaxf(z0, z1);
    float lse = m + logf(expf(z0 - m) + expf(z1 - m));
    out[i * 2 + 0] = z0 - lse;
    out[i * 2 + 1] = z1 - lse;
}

// ---------------- launch ----------------
extern "C" void kernel_launch(void* const* d_in, const int* in_sizes, int n_in,
                              void* d_out, int out_size) {
    const float* x  = (const float*)d_in[0];
    const float* W1 = (const float*)d_in[1];
    const float* b1 = (const float*)d_in[2];
    const float* W2 = (const float*)d_in[3];
    const float* b2 = (const float*)d_in[4];
    const int*   ei = (const int*)d_in[5];
    float* out = (float*)d_out;

    cudaMemcpyToSymbolAsync(cW1, W1, D_IN * D_HID * sizeof(float), 0, cudaMemcpyDeviceToDevice);
    cudaMemcpyToSymbolAsync(cW2, W2, D_HID * D_OUT * sizeof(float), 0, cudaMemcpyDeviceToDevice);
    cudaMemcpyToSymbolAsync(cb1, b1, D_HID * sizeof(float), 0, cudaMemcpyDeviceToDevice);
    cudaMemcpyToSymbolAsync(cb2, b2, D_OUT * sizeof(float), 0, cudaMemcpyDeviceToDevice);

    void* p_deg = nullptr;
    cudaGetSymbolAddress(&p_deg, g_deg);
    cudaMemsetAsync(p_deg, 0, N_NODES * sizeof(int));

    const int T = 256;
    deg_kernel<<<(N_EDGES + T - 1) / T, T>>>(ei);
    gemm1_kernel<<<(N_NODES + 255) / 256, 256>>>(x);
    agg1_kernel<<<(N_EDGES * 4 + 255) / 256, 256>>>(ei);
    project_kernel<<<(N_NODES + T - 1) / T, T>>>();
    agg2_kernel<<<(N_EDGES + T - 1) / T, T>>>(ei);
    final_kernel<<<(N_NODES + T - 1) / T, T>>>(out);
}

// round 17
// speedup vs baseline: 1.1512x; 1.0149x over previous
#include <cuda_runtime.h>
#include <math.h>

#define N_NODES 100000
#define N_EDGES 3200000
#define D_IN    128
#define D_HID   16
#define D_OUT   2

// ---------------- constant weights (copied device-to-device at launch) ----------------
__constant__ float cW1[D_IN * D_HID];
__constant__ float cW2[D_HID * D_OUT];
__constant__ float cb1[D_HID];
__constant__ float cb2[D_OUT];

// ---------------- scratch ----------------
__device__ int   g_deg [N_NODES];           // zeroed via memset; deg = count+1
__device__ float g_dinv[N_NODES];           // computed in gemm1 epilogue
__device__ float g_h1  [N_NODES * D_HID];   // (x @ W1) * dinv
__device__ float g_agg1[N_NODES * D_HID];   // zeroed inside gemm1
__device__ float g_g2  [N_NODES * D_OUT];   // (h2 @ W2) * dinv
__device__ float g_agg2[N_NODES * D_OUT];   // zeroed inside project_kernel

// ---------------- degree histogram: 4 edges per thread via int4 ----------------
__global__ void deg_kernel(const int* __restrict__ ei) {
    int t = blockIdx.x * blockDim.x + threadIdx.x;
    int e0 = t * 4;
    if (e0 >= N_EDGES) return;
    int4 d4 = *(const int4*)&ei[N_EDGES + e0];   // dst slice, 16B aligned
    atomicAdd(&g_deg[d4.x], 1);
    atomicAdd(&g_deg[d4.y], 1);
    atomicAdd(&g_deg[d4.z], 1);
    atomicAdd(&g_deg[d4.w], 1);
}

// ---------------- GEMM1: h1 = (x @ W1) * dinv, one thread per node ----------------
// W1 in constant memory (warp-uniform addresses -> broadcast path). Fully
// unrolled k-loop lets ptxas front-batch the 32 independent LDG.128, raising
// MLP. Epilogue computes dinv and zeroes this node's agg1 row.
__global__ void __launch_bounds__(256) gemm1_kernel(const float* __restrict__ x) {
    const int node = blockIdx.x * 256 + threadIdx.x;
    if (node >= N_NODES) return;
    const float4* xr = (const float4*)(x + (size_t)node * D_IN);

    float acc[D_HID];
#pragma unroll
    for (int j = 0; j < D_HID; j++) acc[j] = 0.0f;

#pragma unroll
    for (int k4 = 0; k4 < D_IN / 4; k4++) {
        float4 xv = xr[k4];
        float xs[4] = {xv.x, xv.y, xv.z, xv.w};
#pragma unroll
        for (int kk = 0; kk < 4; kk++) {
            const float* w = &cW1[(k4 * 4 + kk) * D_HID];
#pragma unroll
            for (int j = 0; j < D_HID; j++)
                acc[j] = fmaf(xs[kk], w[j], acc[j]);
        }
    }

    const float di = rsqrtf((float)(g_deg[node] + 1));
    g_dinv[node] = di;
    float4* out = (float4*)&g_h1[(size_t)node * D_HID];
    float4* az  = (float4*)&g_agg1[(size_t)node * D_HID];
    const float4 z4 = make_float4(0.f, 0.f, 0.f, 0.f);
#pragma unroll
    for (int j4 = 0; j4 < 4; j4++) {
        out[j4] = make_float4(acc[j4 * 4 + 0] * di, acc[j4 * 4 + 1] * di,
                              acc[j4 * 4 + 2] * di, acc[j4 * 4 + 3] * di);
        az[j4]  = z4;
    }
}

// ---------------- vector reductions ----------------
__device__ __forceinline__ void red_v4(float* p, float4 v) {
    asm volatile("red.global.add.v4.f32 [%0], {%1,%2,%3,%4};"
                 :: "l"(p), "f"(v.x), "f"(v.y), "f"(v.z), "f"(v.w) : "memory");
}
__device__ __forceinline__ void red_v2(float* p, float a, float b) {
    asm volatile("red.global.add.v2.f32 [%0], {%1,%2};"
                 :: "l"(p), "f"(a), "f"(b) : "memory");
}

// ----- layer-1 aggregation: 4 lanes per edge (coalesced 64B gather + RED) -----
__global__ void __launch_bounds__(256) agg1_kernel(const int* __restrict__ ei) {
    int gt  = blockIdx.x * 256 + threadIdx.x;
    int e   = gt >> 2;
    int sub = gt & 3;
    if (e >= N_EDGES) return;
    int s = ei[e];
    int d = ei[N_EDGES + e];
    float4 v = *(const float4*)&g_h1[(size_t)s * D_HID + sub * 4];
    red_v4(&g_agg1[(size_t)d * D_HID + sub * 4], v);
}

// ------- fused: h2 = relu(dinv*(agg1 + h1) + b1); g2 = (h2 @ W2)*dinv -------
// Also zeroes g_agg2 for this node (runs strictly before agg2_kernel).
__global__ void project_kernel() {
    int i = blockIdx.x * blockDim.x + threadIdx.x;
    if (i >= N_NODES) return;
    float di = g_dinv[i];
    const float4* a4 = (const float4*)&g_agg1[(size_t)i * D_HID];
    const float4* h4 = (const float4*)&g_h1[(size_t)i * D_HID];
    float z0 = 0.f, z1 = 0.f;
#pragma unroll
    for (int j4 = 0; j4 < 4; j4++) {
        float4 a = a4[j4];
        float4 h = h4[j4];
        float hv[4] = {a.x + h.x, a.y + h.y, a.z + h.z, a.w + h.w};
#pragma unroll
        for (int k = 0; k < 4; k++) {
            int j = j4 * 4 + k;
            float h2 = fmaxf(fmaf(di, hv[k], cb1[j]), 0.f);
            z0 = fmaf(h2, cW2[j * D_OUT + 0], z0);
            z1 = fmaf(h2, cW2[j * D_OUT + 1], z1);
        }
    }
    g_g2[i * 2 + 0] = z0 * di;
    g_g2[i * 2 + 1] = z1 * di;
    *(float2*)&g_agg2[i * 2] = make_float2(0.f, 0.f);
}

// ---------------- layer-2 aggregation: one thread per edge ----------------
__global__ void agg2_kernel(const int* __restrict__ ei) {
    int e = blockIdx.x * blockDim.x + threadIdx.x;
    if (e >= N_EDGES) return;
    int s = ei[e];
    int d = ei[N_EDGES + e];
    float2 m = *(const float2*)&g_g2[s * 2];
    red_v2(&g_agg2[d * 2], m.x, m.y);
}

// ---------------- final: post-scale, bias, log_softmax ----------------
__global__ void final_kernel(float* __restrict__ out) {
    int i = blockIdx.x * blockDim.x + threadIdx.x;
    if (i >= N_NODES) return;
    float di = g_dinv[i];
    float z0 = fmaf(di, g_agg2[i * 2 + 0] + g_g2[i * 2 + 0], cb2[0]);
    float z1 = fmaf(di, g_agg2[i * 2 + 1] + g_g2[i * 2 + 1], cb2[1]);
    float m  = fmaxf(z0, z1);
    float lse = m + logf(expf(z0 - m) + expf(z1 - m));
    out[i * 2 + 0] = z0 - lse;
    out[i * 2 + 1] = z1 - lse;
}

// ---------------- launch ----------------
extern "C" void kernel_launch(void* const* d_in, const int* in_sizes, int n_in,
                              void* d_out, int out_size) {
    const float* x  = (const float*)d_in[0];
    const float* W1 = (const float*)d_in[1];
    const float* b1 = (const float*)d_in[2];
    const float* W2 = (const float*)d_in[3];
    const float* b2 = (const float*)d_in[4];
    const int*   ei = (const int*)d_in[5];
    float* out = (float*)d_out;

    cudaMemcpyToSymbolAsync(cW1, W1, D_IN * D_HID * sizeof(float), 0, cudaMemcpyDeviceToDevice);
    cudaMemcpyToSymbolAsync(cW2, W2, D_HID * D_OUT * sizeof(float), 0, cudaMemcpyDeviceToDevice);
    cudaMemcpyToSymbolAsync(cb1, b1, D_HID * sizeof(float), 0, cudaMemcpyDeviceToDevice);
    cudaMemcpyToSymbolAsync(cb2, b2, D_OUT * sizeof(float), 0, cudaMemcpyDeviceToDevice);

    void* p_deg = nullptr;
    cudaGetSymbolAddress(&p_deg, g_deg);
    cudaMemsetAsync(p_deg, 0, N_NODES * sizeof(int));

    const int T = 256;
    deg_kernel<<<(N_EDGES / 4 + T - 1) / T, T>>>(ei);
    gemm1_kernel<<<(N_NODES + 255) / 256, 256>>>(x);
    agg1_kernel<<<(N_EDGES * 4 + 255) / 256, 256>>>(ei);
    project_kernel<<<(N_NODES + T - 1) / T, T>>>();
    agg2_kernel<<<(N_EDGES + T - 1) / T, T>>>(ei);
    final_kernel<<<(N_NODES + T - 1) / T, T>>>(out);
}